// round 11
// baseline (speedup 1.0000x reference)
#include <cuda_runtime.h>
#include <cuda_bf16.h>
#include <stdint.h>
#include <math.h>

#define M_ROWS 16384
#define KD     1024
#define NS     4096

// ---------------- scratch (device globals) ----------------
__device__ float  g_flat[(size_t)M_ROWS * KD];            // 67 MB (anchor proj)
__device__ float  g_logits[(size_t)M_ROWS * NS];          // 268 MB logits
__device__ __nv_bfloat16 g_pB16[(size_t)M_ROWS * NS];     // 134 MB p bf16
__device__ __nv_bfloat16 g_TtB16[(size_t)NS * NS];        // 33.5 MB T^T bf16
__device__ __nv_bfloat16 g_MtB16[(size_t)NS * NS];        // 33.5 MB M^T bf16
__device__ __nv_bfloat16 g_A3d[(size_t)M_ROWS * 2048];    // 67 MB [2flat_hi|2flat_lo]
__device__ __nv_bfloat16 g_B3d[(size_t)NS * 3072];        // 25 MB [cb_hi|cb_hi|cb_lo]
__device__ __nv_bfloat16 g_A3z[(size_t)M_ROWS * 8192];    // 268 MB [p_hi|p_lo]
__device__ __nv_bfloat16 g_B3z[(size_t)KD * 12288];       // 25 MB [cbT_hi|cbT_hi|cbT_lo]
__device__ float  g_rownorm[M_ROWS];
__device__ float  g_cbnorm[NS];
__device__ float  g_colsumF[KD];
__device__ float  g_colsumC[KD];
__device__ double g_sums[8];  // 0 mag 1 mag2(=Σrn) 3 sigmeta 4 gate 5 align 6 Σcn
__device__ float  g_c1;

__device__ __forceinline__ float sigmoidf_(float x) { return 1.0f / (1.0f + expf(-x)); }
__device__ __forceinline__ void split_bf16(float x, __nv_bfloat16& hi, __nv_bfloat16& lo) {
    hi = __float2bfloat16(x);
    lo = __float2bfloat16(x - __bfloat162float(hi));
}

__device__ double blockReduceD(double v, double* s) {
    int t = threadIdx.x;
    s[t] = v; __syncthreads();
    for (int k = blockDim.x >> 1; k > 0; k >>= 1) {
        if (t < k) s[t] += s[t + k];
        __syncthreads();
    }
    double r = s[0]; __syncthreads();
    return r;
}

__global__ void init_kernel() {
    int t = blockIdx.x * 256 + threadIdx.x;
    if (t < 8) g_sums[t] = 0.0;
    if (t < KD) { g_colsumF[t] = 0.0f; g_colsumC[t] = 0.0f; }
}

// flat = [zr,zi]; A3d = [hi(2a)|lo(2a)] sections; rownorm; mag sums
__global__ __launch_bounds__(256) void prep_kernel(const float* __restrict__ zr,
                                                   const float* __restrict__ zi) {
    __shared__ double sred[256];
    int row = blockIdx.x, tid = threadIdx.x;
    size_t fb = (size_t)row * KD, ab = (size_t)row * 2048;
    double lm = 0.0, lm2 = 0.0;
#pragma unroll
    for (int t = 0; t < 2; t++) {
        int k = tid + t * 256;
        float a = zr[(size_t)row * 512 + k];
        float b = zi[(size_t)row * 512 + k];
        float m2 = a * a + b * b;
        g_flat[fb + k]       = a;
        g_flat[fb + 512 + k] = b;
        __nv_bfloat16 hi, lo;
        split_bf16(2.0f * a, hi, lo);
        g_A3d[ab + k] = hi;        g_A3d[ab + 1024 + k] = lo;
        split_bf16(2.0f * b, hi, lo);
        g_A3d[ab + 512 + k] = hi;  g_A3d[ab + 1536 + k] = lo;
        lm  += (double)sqrtf(m2);
        lm2 += (double)m2;
    }
    double rn = blockReduceD(lm2, sred);
    double sm = blockReduceD(lm, sred);
    if (tid == 0) {
        g_rownorm[row] = (float)rn;
        atomicAdd(&g_sums[0], sm);
        atomicAdd(&g_sums[1], rn);
    }
}

// cbnorm + B3d rows [hi|hi|lo] + Σcn
__global__ __launch_bounds__(256) void cb_rows_kernel(const float* __restrict__ cb) {
    __shared__ double sred[256];
    int n = blockIdx.x, tid = threadIdx.x;
    size_t bb = (size_t)n * 3072;
    double s = 0.0;
#pragma unroll
    for (int t = 0; t < 4; t++) {
        int k = tid + t * 256;
        float v = cb[(size_t)n * KD + k];
        s += (double)(v * v);
        __nv_bfloat16 hi, lo;
        split_bf16(v, hi, lo);
        g_B3d[bb + k] = hi; g_B3d[bb + 1024 + k] = hi; g_B3d[bb + 2048 + k] = lo;
    }
    double r = blockReduceD(s, sred);
    if (tid == 0) {
        g_cbnorm[n] = (float)r;
        atomicAdd(&g_sums[6], r);
    }
}

// column sums for exact d.mean
__global__ void colsumF_kernel() {   // grid (4,16)
    int c = blockIdx.x * 256 + threadIdx.x;
    size_t r0 = (size_t)blockIdx.y * 1024;
    float s = 0.0f;
    for (int r = 0; r < 1024; r++) s += g_flat[(r0 + r) * KD + c];
    atomicAdd(&g_colsumF[c], s);
}
__global__ void colsumC_kernel(const float* __restrict__ cb) {  // grid (4,16)
    int c = blockIdx.x * 256 + threadIdx.x;
    size_t r0 = (size_t)blockIdx.y * 256;
    float s = 0.0f;
    for (int r = 0; r < 256; r++) s += cb[(r0 + r) * KD + c];
    atomicAdd(&g_colsumC[c], s);
}

__global__ void c1_kernel() {
    const double Nm = 8388608.0;
    double s1 = g_sums[0], s2 = g_sums[1];
    double var = (s2 - s1 * s1 / Nm) / (Nm - 1.0);
    double x = var / (1.0 + 1e-6);
    g_c1 = (float)(0.01 * log1p(exp(x)));
}

__global__ __launch_bounds__(256) void conv_p_kernel(const float* __restrict__ in) {
    size_t i = (size_t)blockIdx.x * 256 + threadIdx.x;
    float4 v = ((const float4*)in)[i];
    __nv_bfloat162 lo = __floats2bfloat162_rn(v.x, v.y);
    __nv_bfloat162 hi = __floats2bfloat162_rn(v.z, v.w);
    uint2 u; u.x = *(uint32_t*)&lo; u.y = *(uint32_t*)&hi;
    ((uint2*)g_pB16)[i] = u;
}

template <int DST>
__global__ void transpose_bf16(const float* __restrict__ in) {
    __shared__ float t[32][33];
    int x  = blockIdx.x * 32 + threadIdx.x;
    int y0 = blockIdx.y * 32;
    for (int i = threadIdx.y; i < 32; i += 8)
        t[i][threadIdx.x] = in[(size_t)(y0 + i) * NS + x];
    __syncthreads();
    __nv_bfloat16* outp = DST ? g_MtB16 : g_TtB16;
    int ox  = y0 + threadIdx.x;
    int oy0 = blockIdx.x * 32;
    for (int i = threadIdx.y; i < 32; i += 8)
        outp[(size_t)(oy0 + i) * NS + ox] = __float2bfloat16(t[threadIdx.x][i]);
}

// cb [4096,1024] -> B3z [1024,12288] = [cbT_hi|cbT_hi|cbT_lo]
__global__ void transpose_cb_split(const float* __restrict__ in) {
    __shared__ float t[32][33];
    int x  = blockIdx.x * 32 + threadIdx.x;
    int y0 = blockIdx.y * 32;
    for (int i = threadIdx.y; i < 32; i += 8)
        t[i][threadIdx.x] = in[(size_t)(y0 + i) * KD + x];
    __syncthreads();
    int ox  = y0 + threadIdx.x;
    int oy0 = blockIdx.x * 32;
    for (int i = threadIdx.y; i < 32; i += 8) {
        float v = t[threadIdx.x][i];
        __nv_bfloat16 hi, lo;
        split_bf16(v, hi, lo);
        size_t base = (size_t)(oy0 + i) * 12288;
        g_B3z[base + ox] = hi; g_B3z[base + 4096 + ox] = hi; g_B3z[base + 8192 + ox] = lo;
    }
}

// ---------------- HMMA core: 128x256 block tile, 64x64 warp tile, 3-stage ----------------
__device__ __forceinline__ void mma16816(float* c, uint32_t a0, uint32_t a1, uint32_t a2,
                                         uint32_t a3, uint32_t b0, uint32_t b1) {
    asm volatile(
        "mma.sync.aligned.m16n8k16.row.col.f32.bf16.bf16.f32 "
        "{%0,%1,%2,%3}, {%4,%5,%6,%7}, {%8,%9}, {%0,%1,%2,%3};"
        : "+f"(c[0]), "+f"(c[1]), "+f"(c[2]), "+f"(c[3])
        : "r"(a0), "r"(a1), "r"(a2), "r"(a3), "r"(b0), "r"(b1));
}
__device__ __forceinline__ uint32_t tile_word(const uint8_t* s, int r, int w) {
    return *(const uint32_t*)(s + r * 128 + ((((w >> 2) ^ (r & 7)) << 4) | ((w & 3) << 2)));
}
__device__ __forceinline__ void cp16(void* s, const void* g) {
    uint32_t sa = (uint32_t)__cvta_generic_to_shared(s);
    asm volatile("cp.async.cg.shared.global [%0], [%1], 16;" :: "r"(sa), "l"(g) : "memory");
}
#define STAGE_BYTES 49152

__device__ __forceinline__ void load_tiles2(uint8_t* stage, const uint4* gA, const uint4* gB,
                                            int m0, int n0, int KvA, int KvB,
                                            int itA, int itB, int tid) {
    uint8_t* As = stage;
    uint8_t* Bs = stage + 16384;
#pragma unroll
    for (int l = 0; l < 4; l++) {       // A: 128 rows x 8 uint4
        int i = tid + l * 256;
        int r = i >> 3, c = i & 7;
        cp16(As + r * 128 + ((c ^ (r & 7)) << 4),
             gA + (size_t)(m0 + r) * KvA + (size_t)itA * 8 + c);
    }
#pragma unroll
    for (int l = 0; l < 8; l++) {       // B: 256 rows x 8 uint4
        int i = tid + l * 256;
        int r = i >> 3, c = i & 7;
        cp16(Bs + r * 128 + ((c ^ (r & 7)) << 4),
             gB + (size_t)(n0 + r) * KvB + (size_t)itB * 8 + c);
    }
    asm volatile("cp.async.commit_group;" ::: "memory");
}

// accumulate acc += A[m0..+128] x B[n0..+256]^T over NIT*64 logical k (A k-index wraps at wrapA)
__device__ void gemm_phase(float acc[4][8][4], const __nv_bfloat16* A, const __nv_bfloat16* B,
                           int m0, int n0, int KvA, int KvB, int NIT, int wrapA,
                           uint8_t* smem, int tid, int lane, int wm, int wn) {
    const uint4* gA = (const uint4*)A;
    const uint4* gB = (const uint4*)B;
    int pre = NIT < 2 ? NIT : 2;
    for (int p = 0; p < pre; p++) {
        int ia = p >= wrapA ? p - wrapA : p;
        load_tiles2(smem + p * STAGE_BYTES, gA, gB, m0, n0, KvA, KvB, ia, p, tid);
    }
    for (int it = 0; it < NIT; it++) {
        if (it + 2 < NIT) {
            int nx = it + 2;
            int ia = nx >= wrapA ? nx - wrapA : nx;
            load_tiles2(smem + (nx % 3) * STAGE_BYTES, gA, gB, m0, n0, KvA, KvB, ia, nx, tid);
            asm volatile("cp.async.wait_group 2;" ::: "memory");
        } else {
            asm volatile("cp.async.wait_group 0;" ::: "memory");
        }
        __syncthreads();
        const uint8_t* As = smem + (it % 3) * STAGE_BYTES;
        const uint8_t* Bs = As + 16384;
#pragma unroll
        for (int ks = 0; ks < 4; ks++) {
            int w  = ks * 8 + (lane & 3);
            int w2 = w + 4;
            uint32_t bf[8][2];
#pragma unroll
            for (int nt = 0; nt < 8; nt++) {
                int br = wn * 64 + nt * 8 + (lane >> 2);
                bf[nt][0] = tile_word(Bs, br, w);
                bf[nt][1] = tile_word(Bs, br, w2);
            }
#pragma unroll
            for (int mt = 0; mt < 4; mt++) {
                int ar0 = wm * 64 + mt * 16 + (lane >> 2);
                int ar1 = ar0 + 8;
                uint32_t a0 = tile_word(As, ar0, w);
                uint32_t a1 = tile_word(As, ar1, w);
                uint32_t a2 = tile_word(As, ar0, w2);
                uint32_t a3 = tile_word(As, ar1, w2);
#pragma unroll
                for (int nt = 0; nt < 8; nt++)
                    mma16816(acc[mt][nt], a0, a1, a2, a3, bf[nt][0], bf[nt][1]);
            }
        }
        __syncthreads();
    }
}

// fused: acc = c1*sigmoid(p@T^T tile), then += (2flat)@cb^T tile; logits = acc - rn - cn
__global__ __launch_bounds__(256, 1) void gemm_fused(const __nv_bfloat16* __restrict__ A1,
                                                     const __nv_bfloat16* __restrict__ B1,
                                                     const __nv_bfloat16* __restrict__ A2,
                                                     const __nv_bfloat16* __restrict__ B2) {
    extern __shared__ __align__(16) uint8_t smem[];
    int tid = threadIdx.x, lane = tid & 31, wid = tid >> 5;
    int wm = wid & 1, wn = wid >> 1;
    int m0 = blockIdx.y * 128, n0 = blockIdx.x * 256;

    float acc[4][8][4];
#pragma unroll
    for (int i = 0; i < 4; i++)
#pragma unroll
        for (int j = 0; j < 8; j++)
#pragma unroll
            for (int k = 0; k < 4; k++) acc[i][j][k] = 0.0f;

    // phase 1: graph bias (K=4096)
    gemm_phase(acc, A1, B1, m0, n0, 512, 512, 64, 1 << 30, smem, tid, lane, wm, wn);
    float c1v = g_c1;
#pragma unroll
    for (int i = 0; i < 4; i++)
#pragma unroll
        for (int j = 0; j < 8; j++)
#pragma unroll
            for (int k = 0; k < 4; k++) acc[i][j][k] = c1v * sigmoidf_(acc[i][j][k]);
    // phase 2: += 2*flat@cb (split-bf16, logical K=3072, A wraps at it 32)
    gemm_phase(acc, A2, B2, m0, n0, 256, 384, 48, 32, smem, tid, lane, wm, wn);

#pragma unroll
    for (int mt = 0; mt < 4; mt++) {
        int gr = m0 + wm * 64 + mt * 16 + (lane >> 2);
        float rn0 = g_rownorm[gr], rn1 = g_rownorm[gr + 8];
#pragma unroll
        for (int nt = 0; nt < 8; nt++) {
            int gc = n0 + wn * 64 + nt * 8 + (lane & 3) * 2;
            float cn0 = g_cbnorm[gc], cn1 = g_cbnorm[gc + 1];
            float* p0 = g_logits + (size_t)gr * NS + gc;
            float* p1 = g_logits + (size_t)(gr + 8) * NS + gc;
            p0[0] = acc[mt][nt][0] - rn0 - cn0;
            p0[1] = acc[mt][nt][1] - rn0 - cn1;
            p1[0] = acc[mt][nt][2] - rn1 - cn0;
            p1[1] = acc[mt][nt][3] - rn1 - cn1;
        }
    }
}

// meta bias: g_sums[3] += sum sigmoid(p@M^T)
__global__ __launch_bounds__(256, 1) void gemm_meta(const __nv_bfloat16* __restrict__ A,
                                                    const __nv_bfloat16* __restrict__ B) {
    extern __shared__ __align__(16) uint8_t smem[];
    int tid = threadIdx.x, lane = tid & 31, wid = tid >> 5;
    int wm = wid & 1, wn = wid >> 1;
    int m0 = blockIdx.y * 128, n0 = blockIdx.x * 256;

    float acc[4][8][4];
#pragma unroll
    for (int i = 0; i < 4; i++)
#pragma unroll
        for (int j = 0; j < 8; j++)
#pragma unroll
            for (int k = 0; k < 4; k++) acc[i][j][k] = 0.0f;

    gemm_phase(acc, A, B, m0, n0, 512, 512, 64, 1 << 30, smem, tid, lane, wm, wn);

    float s = 0.0f;
#pragma unroll
    for (int i = 0; i < 4; i++)
#pragma unroll
        for (int j = 0; j < 8; j++)
#pragma unroll
            for (int k = 0; k < 4; k++) s += sigmoidf_(acc[i][j][k]);
    double ds = (double)s;
#pragma unroll
    for (int o = 16; o > 0; o >>= 1)
        ds += __shfl_down_sync(0xffffffff, ds, o);
    if (lane == 0) atomicAdd(&g_sums[3], ds);
}

// z_q = probs@cb (split-bf16, logical K=12288, A wraps at 128)
__global__ __launch_bounds__(256, 1) void gemm_zq(const __nv_bfloat16* __restrict__ A,
                                                  const __nv_bfloat16* __restrict__ B,
                                                  float* __restrict__ outp,
                                                  size_t out_n, int zqMode) {
    extern __shared__ __align__(16) uint8_t smem[];
    int tid = threadIdx.x, lane = tid & 31, wid = tid >> 5;
    int wm = wid & 1, wn = wid >> 1;
    int m0 = blockIdx.y * 128, n0 = blockIdx.x * 256;

    float acc[4][8][4];
#pragma unroll
    for (int i = 0; i < 4; i++)
#pragma unroll
        for (int j = 0; j < 8; j++)
#pragma unroll
            for (int k = 0; k < 4; k++) acc[i][j][k] = 0.0f;

    gemm_phase(acc, A, B, m0, n0, 1024, 1536, 192, 128, smem, tid, lane, wm, wn);

#pragma unroll
    for (int mt = 0; mt < 4; mt++) {
        int gr = m0 + wm * 64 + mt * 16 + (lane >> 2);
#pragma unroll
        for (int nt = 0; nt < 8; nt++) {
            int gc = n0 + wn * 64 + nt * 8 + (lane & 3) * 2;
#pragma unroll
            for (int k = 0; k < 4; k++) {
                int r = gr + (k >> 1) * 8, c = gc + (k & 1);
                size_t o;
                bool valid = true;
                if (zqMode == 0) {
                    o = (c < 512) ? ((size_t)r * 512 + c) * 2
                                  : ((size_t)r * 512 + (c - 512)) * 2 + 1;
                } else if (zqMode == 1) {
                    o = (c < 512) ? ((size_t)r * 512 + c)
                                  : (8388608ULL + (size_t)r * 512 + (c - 512));
                } else {
                    valid = (c < 512);
                    o = (size_t)r * 512 + c;
                }
                if (valid && o < out_n) outp[o] = acc[mt][nt][k];
            }
        }
    }
}

// ---------------- softmax / entropy / argmax / gate + A3z [hi|lo] ----------------
__global__ __launch_bounds__(256) void softmax_kernel(const float* __restrict__ pent,
                                                      float* __restrict__ out,
                                                      size_t out_n,
                                                      size_t offProbs, size_t offHidx,
                                                      size_t offEnt) {
    __shared__ float sf[256];
    __shared__ float sv[256];
    __shared__ int   si[256];
    int row = blockIdx.x, tid = threadIdx.x;
    const float* lrow = g_logits + (size_t)row * NS;
    size_t ab = (size_t)row * 8192;

    float v[16];
    float mx = -3.4e38f;
#pragma unroll
    for (int t = 0; t < 16; t++) {
        v[t] = lrow[tid + t * 256];
        mx = fmaxf(mx, v[t]);
    }
    sf[tid] = mx; __syncthreads();
    for (int s = 128; s > 0; s >>= 1) { if (tid < s) sf[tid] = fmaxf(sf[tid], sf[tid + s]); __syncthreads(); }
    float rowmax = sf[0]; __syncthreads();

    float e[16]; float lsum = 0.0f;
#pragma unroll
    for (int t = 0; t < 16; t++) { e[t] = expf(v[t] - rowmax); lsum += e[t]; }
    sf[tid] = lsum; __syncthreads();
    for (int s = 128; s > 0; s >>= 1) { if (tid < s) sf[tid] += sf[tid + s]; __syncthreads(); }
    float rowsum = sf[0]; __syncthreads();

    float inv = 1.0f / rowsum;
    float ent = 0.0f, pm = -1.0f; int pidx = 0;
#pragma unroll
    for (int t = 0; t < 16; t++) {
        int col = tid + t * 256;
        float p = e[t] * inv;
        __nv_bfloat16 hi, lo;
        split_bf16(p, hi, lo);
        g_A3z[ab + col] = hi; g_A3z[ab + 4096 + col] = lo;
        size_t oo = offProbs + (size_t)row * NS + col;
        if (oo < out_n) out[oo] = p;
        ent -= p * logf(p + 1e-9f);
        if (p > pm) { pm = p; pidx = col; }
    }
    sf[tid] = ent; __syncthreads();
    for (int s = 128; s > 0; s >>= 1) { if (tid < s) sf[tid] += sf[tid + s]; __syncthreads(); }
    float H = sf[0]; __syncthreads();

    sv[tid] = pm; si[tid] = pidx; __syncthreads();
    for (int s = 128; s > 0; s >>= 1) {
        if (tid < s) {
            if (sv[tid + s] > sv[tid] || (sv[tid + s] == sv[tid] && si[tid + s] < si[tid])) {
                sv[tid] = sv[tid + s]; si[tid] = si[tid + s];
            }
        }
        __syncthreads();
    }
    if (tid == 0) {
        if (offHidx + row < out_n) out[offHidx + row] = (float)si[0];
        if (offEnt + row < out_n)  out[offEnt + row]  = H;
        float dH = fabsf(H - pent[row]);
        float gate = sigmoidf_((dH - 0.5f) * 10.0f);
        atomicAdd(&g_sums[4], (double)gate);
    }
}

// ---------------- anchor alignment (probs from out buffer) ----------------
__global__ __launch_bounds__(256) void anchor_kernel(const float* __restrict__ probs,
                                                     const float* __restrict__ EA,
                                                     const float* __restrict__ W,
                                                     const float* __restrict__ bv) {
    __shared__ float sB[256 * 32];
    __shared__ double sred[256];
    int warp = threadIdx.x >> 5, lane = threadIdx.x & 31;
    int r0 = blockIdx.x * 32 + warp * 4;

    float accA[4] = {0.f, 0.f, 0.f, 0.f};
    for (int c = 0; c < NS; c += 256) {
        for (int i = threadIdx.x; i < 256 * 32; i += 256) sB[i] = EA[(size_t)c * 32 + i];
        __syncthreads();
        for (int n = 0; n < 256; n++) {
            float ea = sB[n * 32 + lane];
#pragma unroll
            for (int q = 0; q < 4; q++)
                accA[q] += probs[(size_t)(r0 + q) * NS + c + n] * ea;
        }
        __syncthreads();
    }

    float accP[4];
    float bb = bv[lane];
#pragma unroll
    for (int q = 0; q < 4; q++) accP[q] = bb;
    for (int c = 0; c < KD; c += 256) {
        for (int i = threadIdx.x; i < 256 * 32; i += 256) sB[i] = W[(size_t)c * 32 + i];
        __syncthreads();
        for (int k = 0; k < 256; k++) {
            float w = sB[k * 32 + lane];
#pragma unroll
            for (int q = 0; q < 4; q++)
                accP[q] += g_flat[(size_t)(r0 + q) * KD + c + k] * w;
        }
        __syncthreads();
    }

    double s = 0.0;
#pragma unroll
    for (int q = 0; q < 4; q++) {
        float df = accP[q] - accA[q];
        s += (double)(df * df);
    }
    double r = blockReduceD(s, sred);
    if (threadIdx.x == 0) atomicAdd(&g_sums[5], r);
}

// finalize scalars; d.mean via exact rank-1 identity
__global__ void final_kernel(float* __restrict__ out, size_t out_n,
                             size_t offDmean, size_t offAlign, size_t offTrans) {
    __shared__ double sred[256];
    int t = threadIdx.x;
    double d = 0.0;
    for (int c = t; c < KD; c += 256)
        d += (double)g_colsumF[c] * (double)g_colsumC[c];
    double dot = blockReduceD(d, sred);
    if (t == 0) {
        const double MN = (double)M_ROWS * (double)NS;
        double sum_d = 4096.0 * g_sums[1] + 16384.0 * g_sums[6] - 2.0 * dot;
        if (offDmean < out_n) out[offDmean] = (float)(sum_d / MN);
        double gateMean = g_sums[4] / 16384.0;
        if (offTrans < out_n) out[offTrans] = (float)(gateMean * ((sum_d - g_sums[3]) / MN));
        if (offAlign < out_n) out[offAlign] = (float)(g_sums[5] / (16384.0 * 32.0));
    }
}

// ---------------- host launcher ----------------
extern "C" void kernel_launch(void* const* d_in, const int* in_sizes, int n_in,
                              void* d_out, int out_size) {
    int i8a = -1, i8b = -1, i16a = -1, i16b = -1;
    int iPSD = -1, iPE = -1, iCB = -1, iEA = -1, iW = -1, iB = -1;
    for (int i = 0; i < n_in; i++) {
        int s = in_sizes[i];
        if      (s == 8388608)  { if (i8a < 0) i8a = i; else i8b = i; }
        else if (s == 16777216) { if (i16a < 0) i16a = i; else i16b = i; }
        else if (s == 67108864) iPSD = i;
        else if (s == 16384)    iPE = i;
        else if (s == 4194304)  iCB = i;
        else if (s == 131072)   iEA = i;
        else if (s == 32768)    iW = i;
        else if (s == 32)       iB = i;
    }
    const float* zr    = (const float*)d_in[i8a];
    const float* zi    = (const float*)d_in[i8b];
    const float* pprev = (const float*)d_in[iPSD];
    const float* pent  = (const float*)d_in[iPE];
    const float* cb    = (const float*)d_in[iCB];
    const float* T     = (const float*)d_in[i16a];
    const float* EA    = (const float*)d_in[iEA];
    const float* W     = (const float*)d_in[iW];
    const float* bv    = (const float*)d_in[iB];
    const float* MT    = (const float*)d_in[i16b];
    float* out = (float*)d_out;
    size_t out_n = (size_t)(unsigned int)out_size;

    const size_t OFF_DISABLED = (size_t)1 << 62;
    int zqMode; bool full;
    size_t offProbs, offHidx, offDmean, offEnt, offAlign, offTrans;
    if (out_n == 8388608ULL) {
        zqMode = 2; full = false;
        offProbs = offHidx = offDmean = offEnt = offAlign = offTrans = OFF_DISABLED;
    } else if (out_n == 16777216ULL) {
        zqMode = 1; full = false;
        offProbs = offHidx = offDmean = offEnt = offAlign = offTrans = OFF_DISABLED;
    } else if (out_n == 75530243ULL) {
        zqMode = 2; full = true;
        offProbs = 8388608ULL;
        offHidx  = offProbs + 67108864ULL;
        offDmean = offHidx + 16384ULL;
        offEnt   = offDmean + 1ULL;
        offAlign = offEnt + 16384ULL;
        offTrans = offAlign + 1ULL;
    } else {
        zqMode = 0; full = true;
        offProbs = 16777216ULL;
        offHidx  = offProbs + 67108864ULL;
        offDmean = offHidx + 16384ULL;
        offEnt   = offDmean + 1ULL;
        offAlign = offEnt + 16384ULL;
        offTrans = offAlign + 1ULL;
    }

    void *ppB16 = nullptr, *pTtB = nullptr, *pMtB = nullptr,
         *pA3d = nullptr, *pB3d = nullptr, *pA3z = nullptr, *pB3z = nullptr;
    cudaGetSymbolAddress(&ppB16, g_pB16);
    cudaGetSymbolAddress(&pTtB, g_TtB16);
    cudaGetSymbolAddress(&pMtB, g_MtB16);
    cudaGetSymbolAddress(&pA3d, g_A3d);
    cudaGetSymbolAddress(&pB3d, g_B3d);
    cudaGetSymbolAddress(&pA3z, g_A3z);
    cudaGetSymbolAddress(&pB3z, g_B3z);

    const int SMEM = 3 * STAGE_BYTES;  // 147456
    cudaFuncSetAttribute(gemm_fused, cudaFuncAttributeMaxDynamicSharedMemorySize, SMEM);
    cudaFuncSetAttribute(gemm_meta,  cudaFuncAttributeMaxDynamicSharedMemorySize, SMEM);
    cudaFuncSetAttribute(gemm_zq,    cudaFuncAttributeMaxDynamicSharedMemorySize, SMEM);

    init_kernel<<<8, 256>>>();
    prep_kernel<<<M_ROWS, 256>>>(zr, zi);
    cb_rows_kernel<<<NS, 256>>>(cb);
    colsumF_kernel<<<dim3(4, 16), 256>>>();
    colsumC_kernel<<<dim3(4, 16), 256>>>(cb);
    c1_kernel<<<1, 1>>>();

    conv_p_kernel<<<65536, 256>>>(pprev);
    dim3 tb(32, 8);
    transpose_bf16<0><<<dim3(128, 128), tb>>>(T);
    if (full) transpose_bf16<1><<<dim3(128, 128), tb>>>(MT);
    transpose_cb_split<<<dim3(32, 128), tb>>>(cb);

    // fused: logits = c1*sig(p@T^T) + 2*flat@cb - rn - cn
    gemm_fused<<<dim3(16, 128), 256, SMEM>>>(
        (const __nv_bfloat16*)ppB16, (const __nv_bfloat16*)pTtB,
        (const __nv_bfloat16*)pA3d, (const __nv_bfloat16*)pB3d);
    // meta bias sum
    if (full)
        gemm_meta<<<dim3(16, 128), 256, SMEM>>>(
            (const __nv_bfloat16*)ppB16, (const __nv_bfloat16*)pMtB);
    // softmax + A3z build
    softmax_kernel<<<M_ROWS, 256>>>(pent, out, out_n, offProbs, offHidx, offEnt);
    // z_q
    gemm_zq<<<dim3(4, 128), 256, SMEM>>>(
        (const __nv_bfloat16*)pA3z, (const __nv_bfloat16*)pB3z, out, out_n, zqMode);

    if (full) {
        anchor_kernel<<<512, 256>>>(out + offProbs, EA, W, bv);
        final_kernel<<<1, 256>>>(out, out_n, offDmean, offAlign, offTrans);
    }
}

// round 12
// speedup vs baseline: 1.0005x; 1.0005x over previous
#include <cuda_runtime.h>
#include <cuda_bf16.h>
#include <stdint.h>
#include <math.h>

#define M_ROWS 16384
#define KD     1024
#define NS     4096

// ---------------- scratch (device globals) ----------------
__device__ float  g_flat[(size_t)M_ROWS * KD];            // 67 MB (anchor proj)
__device__ float  g_logits[(size_t)M_ROWS * NS];          // 268 MB logits
__device__ __nv_bfloat16 g_pB16[(size_t)M_ROWS * NS];     // 134 MB p bf16
__device__ __nv_bfloat16 g_TtB16[(size_t)NS * NS];        // 33.5 MB T^T bf16
__device__ __nv_bfloat16 g_MtB16[(size_t)NS * NS];        // 33.5 MB M^T bf16
__device__ __nv_bfloat16 g_A3d[(size_t)M_ROWS * 2048];    // 67 MB [2flat_hi|2flat_lo]
__device__ __nv_bfloat16 g_B3d[(size_t)NS * 3072];        // 25 MB [cb_hi|cb_hi|cb_lo]
__device__ __nv_bfloat16 g_A3z[(size_t)M_ROWS * 8192];    // 268 MB [p_hi|p_lo]
__device__ __nv_bfloat16 g_B3z[(size_t)KD * 12288];       // 25 MB [cbT_hi|cbT_hi|cbT_lo]
__device__ float  g_rownorm[M_ROWS];
__device__ float  g_cbnorm[NS];
__device__ float  g_colsumF[KD];
__device__ float  g_colsumC[KD];
__device__ double g_sums[8];  // 0 mag 1 mag2(=Σrn) 3 sigmeta 4 gate 5 align 6 Σcn
__device__ float  g_c1;

__device__ __forceinline__ float sigmoidf_(float x) { return 1.0f / (1.0f + expf(-x)); }
__device__ __forceinline__ void split_bf16(float x, __nv_bfloat16& hi, __nv_bfloat16& lo) {
    hi = __float2bfloat16(x);
    lo = __float2bfloat16(x - __bfloat162float(hi));
}

__device__ double blockReduceD(double v, double* s) {
    int t = threadIdx.x;
    s[t] = v; __syncthreads();
    for (int k = blockDim.x >> 1; k > 0; k >>= 1) {
        if (t < k) s[t] += s[t + k];
        __syncthreads();
    }
    double r = s[0]; __syncthreads();
    return r;
}

__global__ void init_kernel() {
    int t = blockIdx.x * 256 + threadIdx.x;
    if (t < 8) g_sums[t] = 0.0;
    if (t < KD) { g_colsumF[t] = 0.0f; g_colsumC[t] = 0.0f; }
}

// flat = [zr,zi]; A3d = [hi(2a)|lo(2a)] sections; rownorm; mag sums
__global__ __launch_bounds__(256) void prep_kernel(const float* __restrict__ zr,
                                                   const float* __restrict__ zi) {
    __shared__ double sred[256];
    int row = blockIdx.x, tid = threadIdx.x;
    size_t fb = (size_t)row * KD, ab = (size_t)row * 2048;
    double lm = 0.0, lm2 = 0.0;
#pragma unroll
    for (int t = 0; t < 2; t++) {
        int k = tid + t * 256;
        float a = zr[(size_t)row * 512 + k];
        float b = zi[(size_t)row * 512 + k];
        float m2 = a * a + b * b;
        g_flat[fb + k]       = a;
        g_flat[fb + 512 + k] = b;
        __nv_bfloat16 hi, lo;
        split_bf16(2.0f * a, hi, lo);
        g_A3d[ab + k] = hi;        g_A3d[ab + 1024 + k] = lo;
        split_bf16(2.0f * b, hi, lo);
        g_A3d[ab + 512 + k] = hi;  g_A3d[ab + 1536 + k] = lo;
        lm  += (double)sqrtf(m2);
        lm2 += (double)m2;
    }
    double rn = blockReduceD(lm2, sred);
    double sm = blockReduceD(lm, sred);
    if (tid == 0) {
        g_rownorm[row] = (float)rn;
        atomicAdd(&g_sums[0], sm);
        atomicAdd(&g_sums[1], rn);
    }
}

// cbnorm + B3d rows [hi|hi|lo] + Σcn
__global__ __launch_bounds__(256) void cb_rows_kernel(const float* __restrict__ cb) {
    __shared__ double sred[256];
    int n = blockIdx.x, tid = threadIdx.x;
    size_t bb = (size_t)n * 3072;
    double s = 0.0;
#pragma unroll
    for (int t = 0; t < 4; t++) {
        int k = tid + t * 256;
        float v = cb[(size_t)n * KD + k];
        s += (double)(v * v);
        __nv_bfloat16 hi, lo;
        split_bf16(v, hi, lo);
        g_B3d[bb + k] = hi; g_B3d[bb + 1024 + k] = hi; g_B3d[bb + 2048 + k] = lo;
    }
    double r = blockReduceD(s, sred);
    if (tid == 0) {
        g_cbnorm[n] = (float)r;
        atomicAdd(&g_sums[6], r);
    }
}

// column sums for exact d.mean
__global__ void colsumF_kernel() {   // grid (4,16)
    int c = blockIdx.x * 256 + threadIdx.x;
    size_t r0 = (size_t)blockIdx.y * 1024;
    float s = 0.0f;
    for (int r = 0; r < 1024; r++) s += g_flat[(r0 + r) * KD + c];
    atomicAdd(&g_colsumF[c], s);
}
__global__ void colsumC_kernel(const float* __restrict__ cb) {  // grid (4,16)
    int c = blockIdx.x * 256 + threadIdx.x;
    size_t r0 = (size_t)blockIdx.y * 256;
    float s = 0.0f;
    for (int r = 0; r < 256; r++) s += cb[(r0 + r) * KD + c];
    atomicAdd(&g_colsumC[c], s);
}

__global__ void c1_kernel() {
    const double Nm = 8388608.0;
    double s1 = g_sums[0], s2 = g_sums[1];
    double var = (s2 - s1 * s1 / Nm) / (Nm - 1.0);
    double x = var / (1.0 + 1e-6);
    g_c1 = (float)(0.01 * log1p(exp(x)));
}

__global__ __launch_bounds__(256) void conv_p_kernel(const float* __restrict__ in) {
    size_t i = (size_t)blockIdx.x * 256 + threadIdx.x;
    float4 v = ((const float4*)in)[i];
    __nv_bfloat162 lo = __floats2bfloat162_rn(v.x, v.y);
    __nv_bfloat162 hi = __floats2bfloat162_rn(v.z, v.w);
    uint2 u; u.x = *(uint32_t*)&lo; u.y = *(uint32_t*)&hi;
    ((uint2*)g_pB16)[i] = u;
}

template <int DST>
__global__ void transpose_bf16(const float* __restrict__ in) {
    __shared__ float t[32][33];
    int x  = blockIdx.x * 32 + threadIdx.x;
    int y0 = blockIdx.y * 32;
    for (int i = threadIdx.y; i < 32; i += 8)
        t[i][threadIdx.x] = in[(size_t)(y0 + i) * NS + x];
    __syncthreads();
    __nv_bfloat16* outp = DST ? g_MtB16 : g_TtB16;
    int ox  = y0 + threadIdx.x;
    int oy0 = blockIdx.x * 32;
    for (int i = threadIdx.y; i < 32; i += 8)
        outp[(size_t)(oy0 + i) * NS + ox] = __float2bfloat16(t[threadIdx.x][i]);
}

// cb [4096,1024] -> B3z [1024,12288] = [cbT_hi|cbT_hi|cbT_lo]
__global__ void transpose_cb_split(const float* __restrict__ in) {
    __shared__ float t[32][33];
    int x  = blockIdx.x * 32 + threadIdx.x;
    int y0 = blockIdx.y * 32;
    for (int i = threadIdx.y; i < 32; i += 8)
        t[i][threadIdx.x] = in[(size_t)(y0 + i) * KD + x];
    __syncthreads();
    int ox  = y0 + threadIdx.x;
    int oy0 = blockIdx.x * 32;
    for (int i = threadIdx.y; i < 32; i += 8) {
        float v = t[threadIdx.x][i];
        __nv_bfloat16 hi, lo;
        split_bf16(v, hi, lo);
        size_t base = (size_t)(oy0 + i) * 12288;
        g_B3z[base + ox] = hi; g_B3z[base + 4096 + ox] = hi; g_B3z[base + 8192 + ox] = lo;
    }
}

// ---------------- HMMA core: 128x256 block tile, 64x64 warp tile, 3-stage ----------------
__device__ __forceinline__ void mma16816(float* c, uint32_t a0, uint32_t a1, uint32_t a2,
                                         uint32_t a3, uint32_t b0, uint32_t b1) {
    asm volatile(
        "mma.sync.aligned.m16n8k16.row.col.f32.bf16.bf16.f32 "
        "{%0,%1,%2,%3}, {%4,%5,%6,%7}, {%8,%9}, {%0,%1,%2,%3};"
        : "+f"(c[0]), "+f"(c[1]), "+f"(c[2]), "+f"(c[3])
        : "r"(a0), "r"(a1), "r"(a2), "r"(a3), "r"(b0), "r"(b1));
}
__device__ __forceinline__ uint32_t tile_word(const uint8_t* s, int r, int w) {
    return *(const uint32_t*)(s + r * 128 + ((((w >> 2) ^ (r & 7)) << 4) | ((w & 3) << 2)));
}
__device__ __forceinline__ void cp16(void* s, const void* g) {
    uint32_t sa = (uint32_t)__cvta_generic_to_shared(s);
    asm volatile("cp.async.cg.shared.global [%0], [%1], 16;" :: "r"(sa), "l"(g) : "memory");
}
#define STAGE_BYTES 49152

__device__ __forceinline__ void load_tiles2(uint8_t* stage, const uint4* gA, const uint4* gB,
                                            int m0, int n0, int KvA, int KvB,
                                            int itA, int itB, int tid) {
    uint8_t* As = stage;
    uint8_t* Bs = stage + 16384;
#pragma unroll
    for (int l = 0; l < 4; l++) {       // A: 128 rows x 8 uint4
        int i = tid + l * 256;
        int r = i >> 3, c = i & 7;
        cp16(As + r * 128 + ((c ^ (r & 7)) << 4),
             gA + (size_t)(m0 + r) * KvA + (size_t)itA * 8 + c);
    }
#pragma unroll
    for (int l = 0; l < 8; l++) {       // B: 256 rows x 8 uint4
        int i = tid + l * 256;
        int r = i >> 3, c = i & 7;
        cp16(Bs + r * 128 + ((c ^ (r & 7)) << 4),
             gB + (size_t)(n0 + r) * KvB + (size_t)itB * 8 + c);
    }
    asm volatile("cp.async.commit_group;" ::: "memory");
}

// accumulate acc += A[m0..+128] x B[n0..+256]^T over NIT*64 logical k (A k-index wraps at wrapA)
__device__ void gemm_phase(float acc[4][8][4], const __nv_bfloat16* A, const __nv_bfloat16* B,
                           int m0, int n0, int KvA, int KvB, int NIT, int wrapA,
                           uint8_t* smem, int tid, int lane, int wm, int wn) {
    const uint4* gA = (const uint4*)A;
    const uint4* gB = (const uint4*)B;
    int pre = NIT < 2 ? NIT : 2;
    for (int p = 0; p < pre; p++) {
        int ia = p >= wrapA ? p - wrapA : p;
        load_tiles2(smem + p * STAGE_BYTES, gA, gB, m0, n0, KvA, KvB, ia, p, tid);
    }
    for (int it = 0; it < NIT; it++) {
        if (it + 2 < NIT) {
            int nx = it + 2;
            int ia = nx >= wrapA ? nx - wrapA : nx;
            load_tiles2(smem + (nx % 3) * STAGE_BYTES, gA, gB, m0, n0, KvA, KvB, ia, nx, tid);
            asm volatile("cp.async.wait_group 2;" ::: "memory");
        } else {
            asm volatile("cp.async.wait_group 0;" ::: "memory");
        }
        __syncthreads();
        const uint8_t* As = smem + (it % 3) * STAGE_BYTES;
        const uint8_t* Bs = As + 16384;
#pragma unroll
        for (int ks = 0; ks < 4; ks++) {
            int w  = ks * 8 + (lane & 3);
            int w2 = w + 4;
            uint32_t bf[8][2];
#pragma unroll
            for (int nt = 0; nt < 8; nt++) {
                int br = wn * 64 + nt * 8 + (lane >> 2);
                bf[nt][0] = tile_word(Bs, br, w);
                bf[nt][1] = tile_word(Bs, br, w2);
            }
#pragma unroll
            for (int mt = 0; mt < 4; mt++) {
                int ar0 = wm * 64 + mt * 16 + (lane >> 2);
                int ar1 = ar0 + 8;
                uint32_t a0 = tile_word(As, ar0, w);
                uint32_t a1 = tile_word(As, ar1, w);
                uint32_t a2 = tile_word(As, ar0, w2);
                uint32_t a3 = tile_word(As, ar1, w2);
#pragma unroll
                for (int nt = 0; nt < 8; nt++)
                    mma16816(acc[mt][nt], a0, a1, a2, a3, bf[nt][0], bf[nt][1]);
            }
        }
        __syncthreads();
    }
}

// fused: acc = c1*sigmoid(p@T^T tile), then += (2flat)@cb^T tile; logits = acc - rn - cn
__global__ __launch_bounds__(256, 1) void gemm_fused(const __nv_bfloat16* __restrict__ A1,
                                                     const __nv_bfloat16* __restrict__ B1,
                                                     const __nv_bfloat16* __restrict__ A2,
                                                     const __nv_bfloat16* __restrict__ B2) {
    extern __shared__ __align__(16) uint8_t smem[];
    int tid = threadIdx.x, lane = tid & 31, wid = tid >> 5;
    int wm = wid & 1, wn = wid >> 1;
    int m0 = blockIdx.y * 128, n0 = blockIdx.x * 256;

    float acc[4][8][4];
#pragma unroll
    for (int i = 0; i < 4; i++)
#pragma unroll
        for (int j = 0; j < 8; j++)
#pragma unroll
            for (int k = 0; k < 4; k++) acc[i][j][k] = 0.0f;

    // phase 1: graph bias (K=4096)
    gemm_phase(acc, A1, B1, m0, n0, 512, 512, 64, 1 << 30, smem, tid, lane, wm, wn);
    float c1v = g_c1;
#pragma unroll
    for (int i = 0; i < 4; i++)
#pragma unroll
        for (int j = 0; j < 8; j++)
#pragma unroll
            for (int k = 0; k < 4; k++) acc[i][j][k] = c1v * sigmoidf_(acc[i][j][k]);
    // phase 2: += 2*flat@cb (split-bf16, logical K=3072, A wraps at it 32)
    gemm_phase(acc, A2, B2, m0, n0, 256, 384, 48, 32, smem, tid, lane, wm, wn);

#pragma unroll
    for (int mt = 0; mt < 4; mt++) {
        int gr = m0 + wm * 64 + mt * 16 + (lane >> 2);
        float rn0 = g_rownorm[gr], rn1 = g_rownorm[gr + 8];
#pragma unroll
        for (int nt = 0; nt < 8; nt++) {
            int gc = n0 + wn * 64 + nt * 8 + (lane & 3) * 2;
            float cn0 = g_cbnorm[gc], cn1 = g_cbnorm[gc + 1];
            float* p0 = g_logits + (size_t)gr * NS + gc;
            float* p1 = g_logits + (size_t)(gr + 8) * NS + gc;
            p0[0] = acc[mt][nt][0] - rn0 - cn0;
            p0[1] = acc[mt][nt][1] - rn0 - cn1;
            p1[0] = acc[mt][nt][2] - rn1 - cn0;
            p1[1] = acc[mt][nt][3] - rn1 - cn1;
        }
    }
}

// meta bias: g_sums[3] += sum sigmoid(p@M^T)
__global__ __launch_bounds__(256, 1) void gemm_meta(const __nv_bfloat16* __restrict__ A,
                                                    const __nv_bfloat16* __restrict__ B) {
    extern __shared__ __align__(16) uint8_t smem[];
    int tid = threadIdx.x, lane = tid & 31, wid = tid >> 5;
    int wm = wid & 1, wn = wid >> 1;
    int m0 = blockIdx.y * 128, n0 = blockIdx.x * 256;

    float acc[4][8][4];
#pragma unroll
    for (int i = 0; i < 4; i++)
#pragma unroll
        for (int j = 0; j < 8; j++)
#pragma unroll
            for (int k = 0; k < 4; k++) acc[i][j][k] = 0.0f;

    gemm_phase(acc, A, B, m0, n0, 512, 512, 64, 1 << 30, smem, tid, lane, wm, wn);

    float s = 0.0f;
#pragma unroll
    for (int i = 0; i < 4; i++)
#pragma unroll
        for (int j = 0; j < 8; j++)
#pragma unroll
            for (int k = 0; k < 4; k++) s += sigmoidf_(acc[i][j][k]);
    double ds = (double)s;
#pragma unroll
    for (int o = 16; o > 0; o >>= 1)
        ds += __shfl_down_sync(0xffffffff, ds, o);
    if (lane == 0) atomicAdd(&g_sums[3], ds);
}

// z_q = probs@cb (split-bf16, logical K=12288, A wraps at 128)
__global__ __launch_bounds__(256, 1) void gemm_zq(const __nv_bfloat16* __restrict__ A,
                                                  const __nv_bfloat16* __restrict__ B,
                                                  float* __restrict__ outp,
                                                  size_t out_n, int zqMode) {
    extern __shared__ __align__(16) uint8_t smem[];
    int tid = threadIdx.x, lane = tid & 31, wid = tid >> 5;
    int wm = wid & 1, wn = wid >> 1;
    int m0 = blockIdx.y * 128, n0 = blockIdx.x * 256;

    float acc[4][8][4];
#pragma unroll
    for (int i = 0; i < 4; i++)
#pragma unroll
        for (int j = 0; j < 8; j++)
#pragma unroll
            for (int k = 0; k < 4; k++) acc[i][j][k] = 0.0f;

    gemm_phase(acc, A, B, m0, n0, 1024, 1536, 192, 128, smem, tid, lane, wm, wn);

#pragma unroll
    for (int mt = 0; mt < 4; mt++) {
        int gr = m0 + wm * 64 + mt * 16 + (lane >> 2);
#pragma unroll
        for (int nt = 0; nt < 8; nt++) {
            int gc = n0 + wn * 64 + nt * 8 + (lane & 3) * 2;
#pragma unroll
            for (int k = 0; k < 4; k++) {
                int r = gr + (k >> 1) * 8, c = gc + (k & 1);
                size_t o;
                bool valid = true;
                if (zqMode == 0) {
                    o = (c < 512) ? ((size_t)r * 512 + c) * 2
                                  : ((size_t)r * 512 + (c - 512)) * 2 + 1;
                } else if (zqMode == 1) {
                    o = (c < 512) ? ((size_t)r * 512 + c)
                                  : (8388608ULL + (size_t)r * 512 + (c - 512));
                } else {
                    valid = (c < 512);
                    o = (size_t)r * 512 + c;
                }
                if (valid && o < out_n) outp[o] = acc[mt][nt][k];
            }
        }
    }
}

// ---------------- softmax / entropy / argmax / gate + A3z [hi|lo] ----------------
__global__ __launch_bounds__(256) void softmax_kernel(const float* __restrict__ pent,
                                                      float* __restrict__ out,
                                                      size_t out_n,
                                                      size_t offProbs, size_t offHidx,
                                                      size_t offEnt) {
    __shared__ float sf[256];
    __shared__ float sv[256];
    __shared__ int   si[256];
    int row = blockIdx.x, tid = threadIdx.x;
    const float* lrow = g_logits + (size_t)row * NS;
    size_t ab = (size_t)row * 8192;

    float v[16];
    float mx = -3.4e38f;
#pragma unroll
    for (int t = 0; t < 16; t++) {
        v[t] = lrow[tid + t * 256];
        mx = fmaxf(mx, v[t]);
    }
    sf[tid] = mx; __syncthreads();
    for (int s = 128; s > 0; s >>= 1) { if (tid < s) sf[tid] = fmaxf(sf[tid], sf[tid + s]); __syncthreads(); }
    float rowmax = sf[0]; __syncthreads();

    float e[16]; float lsum = 0.0f;
#pragma unroll
    for (int t = 0; t < 16; t++) { e[t] = expf(v[t] - rowmax); lsum += e[t]; }
    sf[tid] = lsum; __syncthreads();
    for (int s = 128; s > 0; s >>= 1) { if (tid < s) sf[tid] += sf[tid + s]; __syncthreads(); }
    float rowsum = sf[0]; __syncthreads();

    float inv = 1.0f / rowsum;
    float ent = 0.0f, pm = -1.0f; int pidx = 0;
#pragma unroll
    for (int t = 0; t < 16; t++) {
        int col = tid + t * 256;
        float p = e[t] * inv;
        __nv_bfloat16 hi, lo;
        split_bf16(p, hi, lo);
        g_A3z[ab + col] = hi; g_A3z[ab + 4096 + col] = lo;
        size_t oo = offProbs + (size_t)row * NS + col;
        if (oo < out_n) out[oo] = p;
        ent -= p * logf(p + 1e-9f);
        if (p > pm) { pm = p; pidx = col; }
    }
    sf[tid] = ent; __syncthreads();
    for (int s = 128; s > 0; s >>= 1) { if (tid < s) sf[tid] += sf[tid + s]; __syncthreads(); }
    float H = sf[0]; __syncthreads();

    sv[tid] = pm; si[tid] = pidx; __syncthreads();
    for (int s = 128; s > 0; s >>= 1) {
        if (tid < s) {
            if (sv[tid + s] > sv[tid] || (sv[tid + s] == sv[tid] && si[tid + s] < si[tid])) {
                sv[tid] = sv[tid + s]; si[tid] = si[tid + s];
            }
        }
        __syncthreads();
    }
    if (tid == 0) {
        if (offHidx + row < out_n) out[offHidx + row] = (float)si[0];
        if (offEnt + row < out_n)  out[offEnt + row]  = H;
        float dH = fabsf(H - pent[row]);
        float gate = sigmoidf_((dH - 0.5f) * 10.0f);
        atomicAdd(&g_sums[4], (double)gate);
    }
}

// ---------------- anchor alignment (probs from out buffer) ----------------
__global__ __launch_bounds__(256) void anchor_kernel(const float* __restrict__ probs,
                                                     const float* __restrict__ EA,
                                                     const float* __restrict__ W,
                                                     const float* __restrict__ bv) {
    __shared__ float sB[256 * 32];
    __shared__ double sred[256];
    int warp = threadIdx.x >> 5, lane = threadIdx.x & 31;
    int r0 = blockIdx.x * 32 + warp * 4;

    float accA[4] = {0.f, 0.f, 0.f, 0.f};
    for (int c = 0; c < NS; c += 256) {
        for (int i = threadIdx.x; i < 256 * 32; i += 256) sB[i] = EA[(size_t)c * 32 + i];
        __syncthreads();
        for (int n = 0; n < 256; n++) {
            float ea = sB[n * 32 + lane];
#pragma unroll
            for (int q = 0; q < 4; q++)
                accA[q] += probs[(size_t)(r0 + q) * NS + c + n] * ea;
        }
        __syncthreads();
    }

    float accP[4];
    float bb = bv[lane];
#pragma unroll
    for (int q = 0; q < 4; q++) accP[q] = bb;
    for (int c = 0; c < KD; c += 256) {
        for (int i = threadIdx.x; i < 256 * 32; i += 256) sB[i] = W[(size_t)c * 32 + i];
        __syncthreads();
        for (int k = 0; k < 256; k++) {
            float w = sB[k * 32 + lane];
#pragma unroll
            for (int q = 0; q < 4; q++)
                accP[q] += g_flat[(size_t)(r0 + q) * KD + c + k] * w;
        }
        __syncthreads();
    }

    double s = 0.0;
#pragma unroll
    for (int q = 0; q < 4; q++) {
        float df = accP[q] - accA[q];
        s += (double)(df * df);
    }
    double r = blockReduceD(s, sred);
    if (threadIdx.x == 0) atomicAdd(&g_sums[5], r);
}

// finalize scalars; d.mean via exact rank-1 identity
__global__ void final_kernel(float* __restrict__ out, size_t out_n,
                             size_t offDmean, size_t offAlign, size_t offTrans) {
    __shared__ double sred[256];
    int t = threadIdx.x;
    double d = 0.0;
    for (int c = t; c < KD; c += 256)
        d += (double)g_colsumF[c] * (double)g_colsumC[c];
    double dot = blockReduceD(d, sred);
    if (t == 0) {
        const double MN = (double)M_ROWS * (double)NS;
        double sum_d = 4096.0 * g_sums[1] + 16384.0 * g_sums[6] - 2.0 * dot;
        if (offDmean < out_n) out[offDmean] = (float)(sum_d / MN);
        double gateMean = g_sums[4] / 16384.0;
        if (offTrans < out_n) out[offTrans] = (float)(gateMean * ((sum_d - g_sums[3]) / MN));
        if (offAlign < out_n) out[offAlign] = (float)(g_sums[5] / (16384.0 * 32.0));
    }
}

// ---------------- host launcher ----------------
extern "C" void kernel_launch(void* const* d_in, const int* in_sizes, int n_in,
                              void* d_out, int out_size) {
    int i8a = -1, i8b = -1, i16a = -1, i16b = -1;
    int iPSD = -1, iPE = -1, iCB = -1, iEA = -1, iW = -1, iB = -1;
    for (int i = 0; i < n_in; i++) {
        int s = in_sizes[i];
        if      (s == 8388608)  { if (i8a < 0) i8a = i; else i8b = i; }
        else if (s == 16777216) { if (i16a < 0) i16a = i; else i16b = i; }
        else if (s == 67108864) iPSD = i;
        else if (s == 16384)    iPE = i;
        else if (s == 4194304)  iCB = i;
        else if (s == 131072)   iEA = i;
        else if (s == 32768)    iW = i;
        else if (s == 32)       iB = i;
    }
    const float* zr    = (const float*)d_in[i8a];
    const float* zi    = (const float*)d_in[i8b];
    const float* pprev = (const float*)d_in[iPSD];
    const float* pent  = (const float*)d_in[iPE];
    const float* cb    = (const float*)d_in[iCB];
    const float* T     = (const float*)d_in[i16a];
    const float* EA    = (const float*)d_in[iEA];
    const float* W     = (const float*)d_in[iW];
    const float* bv    = (const float*)d_in[iB];
    const float* MT    = (const float*)d_in[i16b];
    float* out = (float*)d_out;
    size_t out_n = (size_t)(unsigned int)out_size;

    const size_t OFF_DISABLED = (size_t)1 << 62;
    int zqMode; bool full;
    size_t offProbs, offHidx, offDmean, offEnt, offAlign, offTrans;
    if (out_n == 8388608ULL) {
        zqMode = 2; full = false;
        offProbs = offHidx = offDmean = offEnt = offAlign = offTrans = OFF_DISABLED;
    } else if (out_n == 16777216ULL) {
        zqMode = 1; full = false;
        offProbs = offHidx = offDmean = offEnt = offAlign = offTrans = OFF_DISABLED;
    } else if (out_n == 75530243ULL) {
        zqMode = 2; full = true;
        offProbs = 8388608ULL;
        offHidx  = offProbs + 67108864ULL;
        offDmean = offHidx + 16384ULL;
        offEnt   = offDmean + 1ULL;
        offAlign = offEnt + 16384ULL;
        offTrans = offAlign + 1ULL;
    } else {
        zqMode = 0; full = true;
        offProbs = 16777216ULL;
        offHidx  = offProbs + 67108864ULL;
        offDmean = offHidx + 16384ULL;
        offEnt   = offDmean + 1ULL;
        offAlign = offEnt + 16384ULL;
        offTrans = offAlign + 1ULL;
    }

    void *ppB16 = nullptr, *pTtB = nullptr, *pMtB = nullptr,
         *pA3d = nullptr, *pB3d = nullptr, *pA3z = nullptr, *pB3z = nullptr;
    cudaGetSymbolAddress(&ppB16, g_pB16);
    cudaGetSymbolAddress(&pTtB, g_TtB16);
    cudaGetSymbolAddress(&pMtB, g_MtB16);
    cudaGetSymbolAddress(&pA3d, g_A3d);
    cudaGetSymbolAddress(&pB3d, g_B3d);
    cudaGetSymbolAddress(&pA3z, g_A3z);
    cudaGetSymbolAddress(&pB3z, g_B3z);

    const int SMEM = 3 * STAGE_BYTES;  // 147456
    cudaFuncSetAttribute(gemm_fused, cudaFuncAttributeMaxDynamicSharedMemorySize, SMEM);
    cudaFuncSetAttribute(gemm_meta,  cudaFuncAttributeMaxDynamicSharedMemorySize, SMEM);
    cudaFuncSetAttribute(gemm_zq,    cudaFuncAttributeMaxDynamicSharedMemorySize, SMEM);

    init_kernel<<<8, 256>>>();
    prep_kernel<<<M_ROWS, 256>>>(zr, zi);
    cb_rows_kernel<<<NS, 256>>>(cb);
    colsumF_kernel<<<dim3(4, 16), 256>>>();
    colsumC_kernel<<<dim3(4, 16), 256>>>(cb);
    c1_kernel<<<1, 1>>>();

    conv_p_kernel<<<65536, 256>>>(pprev);
    dim3 tb(32, 8);
    transpose_bf16<0><<<dim3(128, 128), tb>>>(T);
    if (full) transpose_bf16<1><<<dim3(128, 128), tb>>>(MT);
    transpose_cb_split<<<dim3(32, 128), tb>>>(cb);

    // fused: logits = c1*sig(p@T^T) + 2*flat@cb - rn - cn
    gemm_fused<<<dim3(16, 128), 256, SMEM>>>(
        (const __nv_bfloat16*)ppB16, (const __nv_bfloat16*)pTtB,
        (const __nv_bfloat16*)pA3d, (const __nv_bfloat16*)pB3d);
    // meta bias sum
    if (full)
        gemm_meta<<<dim3(16, 128), 256, SMEM>>>(
            (const __nv_bfloat16*)ppB16, (const __nv_bfloat16*)pMtB);
    // softmax + A3z build
    softmax_kernel<<<M_ROWS, 256>>>(pent, out, out_n, offProbs, offHidx, offEnt);
    // z_q
    gemm_zq<<<dim3(4, 128), 256, SMEM>>>(
        (const __nv_bfloat16*)pA3z, (const __nv_bfloat16*)pB3z, out, out_n, zqMode);

    if (full) {
        anchor_kernel<<<512, 256>>>(out + offProbs, EA, W, bv);
        final_kernel<<<1, 256>>>(out, out_n, offDmean, offAlign, offTrans);
    }
}

// round 15
// speedup vs baseline: 1.0022x; 1.0017x over previous
#include <cuda_runtime.h>
#include <cuda_bf16.h>
#include <stdint.h>
#include <math.h>

#define M_ROWS 16384
#define KD     1024
#define NS     4096

// ---------------- scratch (device globals) ----------------
__device__ float  g_flat[(size_t)M_ROWS * KD];            // 67 MB (anchor proj)
__device__ float  g_logits[(size_t)M_ROWS * NS];          // 268 MB logits
__device__ __nv_bfloat16 g_pB16[(size_t)M_ROWS * NS];     // 134 MB p bf16
__device__ __nv_bfloat16 g_TtB16[(size_t)NS * NS];        // 33.5 MB T^T bf16
__device__ __nv_bfloat16 g_MtB16[(size_t)NS * NS];        // 33.5 MB M^T bf16
__device__ __nv_bfloat16 g_A3d[(size_t)M_ROWS * 2048];    // 67 MB [2flat_hi|2flat_lo]
__device__ __nv_bfloat16 g_B3d[(size_t)NS * 3072];        // 25 MB [cb_hi|cb_hi|cb_lo]
__device__ __nv_bfloat16 g_A3z[(size_t)M_ROWS * 8192];    // 268 MB [p_hi|p_lo]
__device__ __nv_bfloat16 g_B3z[(size_t)KD * 12288];       // 25 MB [cbT_hi|cbT_hi|cbT_lo]
__device__ float  g_rownorm[M_ROWS];
__device__ float  g_cbnorm[NS];
__device__ float  g_colsumF[KD];
__device__ float  g_colsumC[KD];
__device__ double g_sums[8];  // 0 mag 1 mag2(=Σrn) 3 sigmeta 4 gate 5 align 6 Σcn
__device__ float  g_c1;

__device__ __forceinline__ float sigmoidf_(float x) { return 1.0f / (1.0f + expf(-x)); }
__device__ __forceinline__ void split_bf16(float x, __nv_bfloat16& hi, __nv_bfloat16& lo) {
    hi = __float2bfloat16(x);
    lo = __float2bfloat16(x - __bfloat162float(hi));
}

__device__ double blockReduceD(double v, double* s) {
    int t = threadIdx.x;
    s[t] = v; __syncthreads();
    for (int k = blockDim.x >> 1; k > 0; k >>= 1) {
        if (t < k) s[t] += s[t + k];
        __syncthreads();
    }
    double r = s[0]; __syncthreads();
    return r;
}

__global__ void init_kernel() {
    int t = blockIdx.x * 256 + threadIdx.x;
    if (t < 8) g_sums[t] = 0.0;
    if (t < KD) { g_colsumF[t] = 0.0f; g_colsumC[t] = 0.0f; }
}

// flat = [zr,zi]; A3d = [hi(2a)|lo(2a)] sections; rownorm; mag sums
__global__ __launch_bounds__(256) void prep_kernel(const float* __restrict__ zr,
                                                   const float* __restrict__ zi) {
    __shared__ double sred[256];
    int row = blockIdx.x, tid = threadIdx.x;
    size_t fb = (size_t)row * KD, ab = (size_t)row * 2048;
    double lm = 0.0, lm2 = 0.0;
#pragma unroll
    for (int t = 0; t < 2; t++) {
        int k = tid + t * 256;
        float a = zr[(size_t)row * 512 + k];
        float b = zi[(size_t)row * 512 + k];
        float m2 = a * a + b * b;
        g_flat[fb + k]       = a;
        g_flat[fb + 512 + k] = b;
        __nv_bfloat16 hi, lo;
        split_bf16(2.0f * a, hi, lo);
        g_A3d[ab + k] = hi;        g_A3d[ab + 1024 + k] = lo;
        split_bf16(2.0f * b, hi, lo);
        g_A3d[ab + 512 + k] = hi;  g_A3d[ab + 1536 + k] = lo;
        lm  += (double)sqrtf(m2);
        lm2 += (double)m2;
    }
    double rn = blockReduceD(lm2, sred);
    double sm = blockReduceD(lm, sred);
    if (tid == 0) {
        g_rownorm[row] = (float)rn;
        atomicAdd(&g_sums[0], sm);
        atomicAdd(&g_sums[1], rn);
    }
}

// cbnorm + B3d rows [hi|hi|lo] + Σcn
__global__ __launch_bounds__(256) void cb_rows_kernel(const float* __restrict__ cb) {
    __shared__ double sred[256];
    int n = blockIdx.x, tid = threadIdx.x;
    size_t bb = (size_t)n * 3072;
    double s = 0.0;
#pragma unroll
    for (int t = 0; t < 4; t++) {
        int k = tid + t * 256;
        float v = cb[(size_t)n * KD + k];
        s += (double)(v * v);
        __nv_bfloat16 hi, lo;
        split_bf16(v, hi, lo);
        g_B3d[bb + k] = hi; g_B3d[bb + 1024 + k] = hi; g_B3d[bb + 2048 + k] = lo;
    }
    double r = blockReduceD(s, sred);
    if (tid == 0) {
        g_cbnorm[n] = (float)r;
        atomicAdd(&g_sums[6], r);
    }
}

// column sums for exact d.mean
__global__ void colsumF_kernel() {   // grid (4,16)
    int c = blockIdx.x * 256 + threadIdx.x;
    size_t r0 = (size_t)blockIdx.y * 1024;
    float s = 0.0f;
    for (int r = 0; r < 1024; r++) s += g_flat[(r0 + r) * KD + c];
    atomicAdd(&g_colsumF[c], s);
}
__global__ void colsumC_kernel(const float* __restrict__ cb) {  // grid (4,16)
    int c = blockIdx.x * 256 + threadIdx.x;
    size_t r0 = (size_t)blockIdx.y * 256;
    float s = 0.0f;
    for (int r = 0; r < 256; r++) s += cb[(r0 + r) * KD + c];
    atomicAdd(&g_colsumC[c], s);
}

__global__ void c1_kernel() {
    const double Nm = 8388608.0;
    double s1 = g_sums[0], s2 = g_sums[1];
    double var = (s2 - s1 * s1 / Nm) / (Nm - 1.0);
    double x = var / (1.0 + 1e-6);
    g_c1 = (float)(0.01 * log1p(exp(x)));
}

__global__ __launch_bounds__(256) void conv_p_kernel(const float* __restrict__ in) {
    size_t i = (size_t)blockIdx.x * 256 + threadIdx.x;
    float4 v = ((const float4*)in)[i];
    __nv_bfloat162 lo = __floats2bfloat162_rn(v.x, v.y);
    __nv_bfloat162 hi = __floats2bfloat162_rn(v.z, v.w);
    uint2 u; u.x = *(uint32_t*)&lo; u.y = *(uint32_t*)&hi;
    ((uint2*)g_pB16)[i] = u;
}

template <int DST>
__global__ void transpose_bf16(const float* __restrict__ in) {
    __shared__ float t[32][33];
    int x  = blockIdx.x * 32 + threadIdx.x;
    int y0 = blockIdx.y * 32;
    for (int i = threadIdx.y; i < 32; i += 8)
        t[i][threadIdx.x] = in[(size_t)(y0 + i) * NS + x];
    __syncthreads();
    __nv_bfloat16* outp = DST ? g_MtB16 : g_TtB16;
    int ox  = y0 + threadIdx.x;
    int oy0 = blockIdx.x * 32;
    for (int i = threadIdx.y; i < 32; i += 8)
        outp[(size_t)(oy0 + i) * NS + ox] = __float2bfloat16(t[threadIdx.x][i]);
}

// cb [4096,1024] -> B3z [1024,12288] = [cbT_hi|cbT_hi|cbT_lo]
__global__ void transpose_cb_split(const float* __restrict__ in) {
    __shared__ float t[32][33];
    int x  = blockIdx.x * 32 + threadIdx.x;
    int y0 = blockIdx.y * 32;
    for (int i = threadIdx.y; i < 32; i += 8)
        t[i][threadIdx.x] = in[(size_t)(y0 + i) * KD + x];
    __syncthreads();
    int ox  = y0 + threadIdx.x;
    int oy0 = blockIdx.x * 32;
    for (int i = threadIdx.y; i < 32; i += 8) {
        float v = t[threadIdx.x][i];
        __nv_bfloat16 hi, lo;
        split_bf16(v, hi, lo);
        size_t base = (size_t)(oy0 + i) * 12288;
        g_B3z[base + ox] = hi; g_B3z[base + 4096 + ox] = hi; g_B3z[base + 8192 + ox] = lo;
    }
}

// ---------------- HMMA core: 128x256 block tile, 64x64 warp tile, 3-stage ----------------
__device__ __forceinline__ void mma16816(float* c, uint32_t a0, uint32_t a1, uint32_t a2,
                                         uint32_t a3, uint32_t b0, uint32_t b1) {
    asm volatile(
        "mma.sync.aligned.m16n8k16.row.col.f32.bf16.bf16.f32 "
        "{%0,%1,%2,%3}, {%4,%5,%6,%7}, {%8,%9}, {%0,%1,%2,%3};"
        : "+f"(c[0]), "+f"(c[1]), "+f"(c[2]), "+f"(c[3])
        : "r"(a0), "r"(a1), "r"(a2), "r"(a3), "r"(b0), "r"(b1));
}
__device__ __forceinline__ uint32_t tile_word(const uint8_t* s, int r, int w) {
    return *(const uint32_t*)(s + r * 128 + ((((w >> 2) ^ (r & 7)) << 4) | ((w & 3) << 2)));
}
__device__ __forceinline__ void cp16(void* s, const void* g) {
    uint32_t sa = (uint32_t)__cvta_generic_to_shared(s);
    asm volatile("cp.async.cg.shared.global [%0], [%1], 16;" :: "r"(sa), "l"(g) : "memory");
}
#define STAGE_BYTES 49152

__device__ __forceinline__ void load_tiles2(uint8_t* stage, const uint4* gA, const uint4* gB,
                                            int m0, int n0, int KvA, int KvB,
                                            int itA, int itB, int tid) {
    uint8_t* As = stage;
    uint8_t* Bs = stage + 16384;
#pragma unroll
    for (int l = 0; l < 4; l++) {       // A: 128 rows x 8 uint4
        int i = tid + l * 256;
        int r = i >> 3, c = i & 7;
        cp16(As + r * 128 + ((c ^ (r & 7)) << 4),
             gA + (size_t)(m0 + r) * KvA + (size_t)itA * 8 + c);
    }
#pragma unroll
    for (int l = 0; l < 8; l++) {       // B: 256 rows x 8 uint4
        int i = tid + l * 256;
        int r = i >> 3, c = i & 7;
        cp16(Bs + r * 128 + ((c ^ (r & 7)) << 4),
             gB + (size_t)(n0 + r) * KvB + (size_t)itB * 8 + c);
    }
    asm volatile("cp.async.commit_group;" ::: "memory");
}

// accumulate acc += A[m0..+128] x B[n0..+256]^T over NIT*64 logical k (A k-index wraps at wrapA)
__device__ void gemm_phase(float acc[4][8][4], const __nv_bfloat16* A, const __nv_bfloat16* B,
                           int m0, int n0, int KvA, int KvB, int NIT, int wrapA,
                           uint8_t* smem, int tid, int lane, int wm, int wn) {
    const uint4* gA = (const uint4*)A;
    const uint4* gB = (const uint4*)B;
    int pre = NIT < 2 ? NIT : 2;
    for (int p = 0; p < pre; p++) {
        int ia = p >= wrapA ? p - wrapA : p;
        load_tiles2(smem + p * STAGE_BYTES, gA, gB, m0, n0, KvA, KvB, ia, p, tid);
    }
    for (int it = 0; it < NIT; it++) {
        if (it + 2 < NIT) {
            int nx = it + 2;
            int ia = nx >= wrapA ? nx - wrapA : nx;
            load_tiles2(smem + (nx % 3) * STAGE_BYTES, gA, gB, m0, n0, KvA, KvB, ia, nx, tid);
            asm volatile("cp.async.wait_group 2;" ::: "memory");
        } else {
            asm volatile("cp.async.wait_group 0;" ::: "memory");
        }
        __syncthreads();
        const uint8_t* As = smem + (it % 3) * STAGE_BYTES;
        const uint8_t* Bs = As + 16384;
#pragma unroll
        for (int ks = 0; ks < 4; ks++) {
            int w  = ks * 8 + (lane & 3);
            int w2 = w + 4;
            uint32_t bf[8][2];
#pragma unroll
            for (int nt = 0; nt < 8; nt++) {
                int br = wn * 64 + nt * 8 + (lane >> 2);
                bf[nt][0] = tile_word(Bs, br, w);
                bf[nt][1] = tile_word(Bs, br, w2);
            }
#pragma unroll
            for (int mt = 0; mt < 4; mt++) {
                int ar0 = wm * 64 + mt * 16 + (lane >> 2);
                int ar1 = ar0 + 8;
                uint32_t a0 = tile_word(As, ar0, w);
                uint32_t a1 = tile_word(As, ar1, w);
                uint32_t a2 = tile_word(As, ar0, w2);
                uint32_t a3 = tile_word(As, ar1, w2);
#pragma unroll
                for (int nt = 0; nt < 8; nt++)
                    mma16816(acc[mt][nt], a0, a1, a2, a3, bf[nt][0], bf[nt][1]);
            }
        }
        __syncthreads();
    }
}

// fused: acc = c1*sigmoid(p@T^T tile), then += (2flat)@cb^T tile; logits = acc - rn - cn
__global__ __launch_bounds__(256, 1) void gemm_fused(const __nv_bfloat16* __restrict__ A1,
                                                     const __nv_bfloat16* __restrict__ B1,
                                                     const __nv_bfloat16* __restrict__ A2,
                                                     const __nv_bfloat16* __restrict__ B2) {
    extern __shared__ __align__(16) uint8_t smem[];
    int tid = threadIdx.x, lane = tid & 31, wid = tid >> 5;
    int wm = wid & 1, wn = wid >> 1;
    int m0 = blockIdx.y * 128, n0 = blockIdx.x * 256;

    float acc[4][8][4];
#pragma unroll
    for (int i = 0; i < 4; i++)
#pragma unroll
        for (int j = 0; j < 8; j++)
#pragma unroll
            for (int k = 0; k < 4; k++) acc[i][j][k] = 0.0f;

    // phase 1: graph bias (K=4096)
    gemm_phase(acc, A1, B1, m0, n0, 512, 512, 64, 1 << 30, smem, tid, lane, wm, wn);
    float c1v = g_c1;
#pragma unroll
    for (int i = 0; i < 4; i++)
#pragma unroll
        for (int j = 0; j < 8; j++)
#pragma unroll
            for (int k = 0; k < 4; k++) acc[i][j][k] = c1v * sigmoidf_(acc[i][j][k]);
    // phase 2: += 2*flat@cb (split-bf16, logical K=3072, A wraps at it 32)
    gemm_phase(acc, A2, B2, m0, n0, 256, 384, 48, 32, smem, tid, lane, wm, wn);

#pragma unroll
    for (int mt = 0; mt < 4; mt++) {
        int gr = m0 + wm * 64 + mt * 16 + (lane >> 2);
        float rn0 = g_rownorm[gr], rn1 = g_rownorm[gr + 8];
#pragma unroll
        for (int nt = 0; nt < 8; nt++) {
            int gc = n0 + wn * 64 + nt * 8 + (lane & 3) * 2;
            float cn0 = g_cbnorm[gc], cn1 = g_cbnorm[gc + 1];
            float* p0 = g_logits + (size_t)gr * NS + gc;
            float* p1 = g_logits + (size_t)(gr + 8) * NS + gc;
            p0[0] = acc[mt][nt][0] - rn0 - cn0;
            p0[1] = acc[mt][nt][1] - rn0 - cn1;
            p1[0] = acc[mt][nt][2] - rn1 - cn0;
            p1[1] = acc[mt][nt][3] - rn1 - cn1;
        }
    }
}

// meta bias: g_sums[3] += sum sigmoid(p@M^T)
__global__ __launch_bounds__(256, 1) void gemm_meta(const __nv_bfloat16* __restrict__ A,
                                                    const __nv_bfloat16* __restrict__ B) {
    extern __shared__ __align__(16) uint8_t smem[];
    int tid = threadIdx.x, lane = tid & 31, wid = tid >> 5;
    int wm = wid & 1, wn = wid >> 1;
    int m0 = blockIdx.y * 128, n0 = blockIdx.x * 256;

    float acc[4][8][4];
#pragma unroll
    for (int i = 0; i < 4; i++)
#pragma unroll
        for (int j = 0; j < 8; j++)
#pragma unroll
            for (int k = 0; k < 4; k++) acc[i][j][k] = 0.0f;

    gemm_phase(acc, A, B, m0, n0, 512, 512, 64, 1 << 30, smem, tid, lane, wm, wn);

    float s = 0.0f;
#pragma unroll
    for (int i = 0; i < 4; i++)
#pragma unroll
        for (int j = 0; j < 8; j++)
#pragma unroll
            for (int k = 0; k < 4; k++) s += sigmoidf_(acc[i][j][k]);
    double ds = (double)s;
#pragma unroll
    for (int o = 16; o > 0; o >>= 1)
        ds += __shfl_down_sync(0xffffffff, ds, o);
    if (lane == 0) atomicAdd(&g_sums[3], ds);
}

// z_q = probs@cb (split-bf16, logical K=12288, A wraps at 128)
__global__ __launch_bounds__(256, 1) void gemm_zq(const __nv_bfloat16* __restrict__ A,
                                                  const __nv_bfloat16* __restrict__ B,
                                                  float* __restrict__ outp,
                                                  size_t out_n, int zqMode) {
    extern __shared__ __align__(16) uint8_t smem[];
    int tid = threadIdx.x, lane = tid & 31, wid = tid >> 5;
    int wm = wid & 1, wn = wid >> 1;
    int m0 = blockIdx.y * 128, n0 = blockIdx.x * 256;

    float acc[4][8][4];
#pragma unroll
    for (int i = 0; i < 4; i++)
#pragma unroll
        for (int j = 0; j < 8; j++)
#pragma unroll
            for (int k = 0; k < 4; k++) acc[i][j][k] = 0.0f;

    gemm_phase(acc, A, B, m0, n0, 1024, 1536, 192, 128, smem, tid, lane, wm, wn);

#pragma unroll
    for (int mt = 0; mt < 4; mt++) {
        int gr = m0 + wm * 64 + mt * 16 + (lane >> 2);
#pragma unroll
        for (int nt = 0; nt < 8; nt++) {
            int gc = n0 + wn * 64 + nt * 8 + (lane & 3) * 2;
#pragma unroll
            for (int k = 0; k < 4; k++) {
                int r = gr + (k >> 1) * 8, c = gc + (k & 1);
                size_t o;
                bool valid = true;
                if (zqMode == 0) {
                    o = (c < 512) ? ((size_t)r * 512 + c) * 2
                                  : ((size_t)r * 512 + (c - 512)) * 2 + 1;
                } else if (zqMode == 1) {
                    o = (c < 512) ? ((size_t)r * 512 + c)
                                  : (8388608ULL + (size_t)r * 512 + (c - 512));
                } else {
                    valid = (c < 512);
                    o = (size_t)r * 512 + c;
                }
                if (valid && o < out_n) outp[o] = acc[mt][nt][k];
            }
        }
    }
}

// ---------------- softmax / entropy / argmax / gate + A3z [hi|lo] ----------------
__global__ __launch_bounds__(256) void softmax_kernel(const float* __restrict__ pent,
                                                      float* __restrict__ out,
                                                      size_t out_n,
                                                      size_t offProbs, size_t offHidx,
                                                      size_t offEnt) {
    __shared__ float sf[256];
    __shared__ float sv[256];
    __shared__ int   si[256];
    int row = blockIdx.x, tid = threadIdx.x;
    const float* lrow = g_logits + (size_t)row * NS;
    size_t ab = (size_t)row * 8192;

    float v[16];
    float mx = -3.4e38f;
#pragma unroll
    for (int t = 0; t < 16; t++) {
        v[t] = lrow[tid + t * 256];
        mx = fmaxf(mx, v[t]);
    }
    sf[tid] = mx; __syncthreads();
    for (int s = 128; s > 0; s >>= 1) { if (tid < s) sf[tid] = fmaxf(sf[tid], sf[tid + s]); __syncthreads(); }
    float rowmax = sf[0]; __syncthreads();

    float e[16]; float lsum = 0.0f;
#pragma unroll
    for (int t = 0; t < 16; t++) { e[t] = expf(v[t] - rowmax); lsum += e[t]; }
    sf[tid] = lsum; __syncthreads();
    for (int s = 128; s > 0; s >>= 1) { if (tid < s) sf[tid] += sf[tid + s]; __syncthreads(); }
    float rowsum = sf[0]; __syncthreads();

    float inv = 1.0f / rowsum;
    float ent = 0.0f, pm = -1.0f; int pidx = 0;
#pragma unroll
    for (int t = 0; t < 16; t++) {
        int col = tid + t * 256;
        float p = e[t] * inv;
        __nv_bfloat16 hi, lo;
        split_bf16(p, hi, lo);
        g_A3z[ab + col] = hi; g_A3z[ab + 4096 + col] = lo;
        size_t oo = offProbs + (size_t)row * NS + col;
        if (oo < out_n) out[oo] = p;
        ent -= p * logf(p + 1e-9f);
        if (p > pm) { pm = p; pidx = col; }
    }
    sf[tid] = ent; __syncthreads();
    for (int s = 128; s > 0; s >>= 1) { if (tid < s) sf[tid] += sf[tid + s]; __syncthreads(); }
    float H = sf[0]; __syncthreads();

    sv[tid] = pm; si[tid] = pidx; __syncthreads();
    for (int s = 128; s > 0; s >>= 1) {
        if (tid < s) {
            if (sv[tid + s] > sv[tid] || (sv[tid + s] == sv[tid] && si[tid + s] < si[tid])) {
                sv[tid] = sv[tid + s]; si[tid] = si[tid + s];
            }
        }
        __syncthreads();
    }
    if (tid == 0) {
        if (offHidx + row < out_n) out[offHidx + row] = (float)si[0];
        if (offEnt + row < out_n)  out[offEnt + row]  = H;
        float dH = fabsf(H - pent[row]);
        float gate = sigmoidf_((dH - 0.5f) * 10.0f);
        atomicAdd(&g_sums[4], (double)gate);
    }
}

// ---------------- anchor alignment (probs from out buffer) ----------------
__global__ __launch_bounds__(256) void anchor_kernel(const float* __restrict__ probs,
                                                     const float* __restrict__ EA,
                                                     const float* __restrict__ W,
                                                     const float* __restrict__ bv) {
    __shared__ float sB[256 * 32];
    __shared__ double sred[256];
    int warp = threadIdx.x >> 5, lane = threadIdx.x & 31;
    int r0 = blockIdx.x * 32 + warp * 4;

    float accA[4] = {0.f, 0.f, 0.f, 0.f};
    for (int c = 0; c < NS; c += 256) {
        for (int i = threadIdx.x; i < 256 * 32; i += 256) sB[i] = EA[(size_t)c * 32 + i];
        __syncthreads();
        for (int n = 0; n < 256; n++) {
            float ea = sB[n * 32 + lane];
#pragma unroll
            for (int q = 0; q < 4; q++)
                accA[q] += probs[(size_t)(r0 + q) * NS + c + n] * ea;
        }
        __syncthreads();
    }

    float accP[4];
    float bb = bv[lane];
#pragma unroll
    for (int q = 0; q < 4; q++) accP[q] = bb;
    for (int c = 0; c < KD; c += 256) {
        for (int i = threadIdx.x; i < 256 * 32; i += 256) sB[i] = W[(size_t)c * 32 + i];
        __syncthreads();
        for (int k = 0; k < 256; k++) {
            float w = sB[k * 32 + lane];
#pragma unroll
            for (int q = 0; q < 4; q++)
                accP[q] += g_flat[(size_t)(r0 + q) * KD + c + k] * w;
        }
        __syncthreads();
    }

    double s = 0.0;
#pragma unroll
    for (int q = 0; q < 4; q++) {
        float df = accP[q] - accA[q];
        s += (double)(df * df);
    }
    double r = blockReduceD(s, sred);
    if (threadIdx.x == 0) atomicAdd(&g_sums[5], r);
}

// finalize scalars; d.mean via exact rank-1 identity
__global__ void final_kernel(float* __restrict__ out, size_t out_n,
                             size_t offDmean, size_t offAlign, size_t offTrans) {
    __shared__ double sred[256];
    int t = threadIdx.x;
    double d = 0.0;
    for (int c = t; c < KD; c += 256)
        d += (double)g_colsumF[c] * (double)g_colsumC[c];
    double dot = blockReduceD(d, sred);
    if (t == 0) {
        const double MN = (double)M_ROWS * (double)NS;
        double sum_d = 4096.0 * g_sums[1] + 16384.0 * g_sums[6] - 2.0 * dot;
        if (offDmean < out_n) out[offDmean] = (float)(sum_d / MN);
        double gateMean = g_sums[4] / 16384.0;
        if (offTrans < out_n) out[offTrans] = (float)(gateMean * ((sum_d - g_sums[3]) / MN));
        if (offAlign < out_n) out[offAlign] = (float)(g_sums[5] / (16384.0 * 32.0));
    }
}

// ---------------- host launcher ----------------
extern "C" void kernel_launch(void* const* d_in, const int* in_sizes, int n_in,
                              void* d_out, int out_size) {
    int i8a = -1, i8b = -1, i16a = -1, i16b = -1;
    int iPSD = -1, iPE = -1, iCB = -1, iEA = -1, iW = -1, iB = -1;
    for (int i = 0; i < n_in; i++) {
        int s = in_sizes[i];
        if      (s == 8388608)  { if (i8a < 0) i8a = i; else i8b = i; }
        else if (s == 16777216) { if (i16a < 0) i16a = i; else i16b = i; }
        else if (s == 67108864) iPSD = i;
        else if (s == 16384)    iPE = i;
        else if (s == 4194304)  iCB = i;
        else if (s == 131072)   iEA = i;
        else if (s == 32768)    iW = i;
        else if (s == 32)       iB = i;
    }
    const float* zr    = (const float*)d_in[i8a];
    const float* zi    = (const float*)d_in[i8b];
    const float* pprev = (const float*)d_in[iPSD];
    const float* pent  = (const float*)d_in[iPE];
    const float* cb    = (const float*)d_in[iCB];
    const float* T     = (const float*)d_in[i16a];
    const float* EA    = (const float*)d_in[iEA];
    const float* W     = (const float*)d_in[iW];
    const float* bv    = (const float*)d_in[iB];
    const float* MT    = (const float*)d_in[i16b];
    float* out = (float*)d_out;
    size_t out_n = (size_t)(unsigned int)out_size;

    const size_t OFF_DISABLED = (size_t)1 << 62;
    int zqMode; bool full;
    size_t offProbs, offHidx, offDmean, offEnt, offAlign, offTrans;
    if (out_n == 8388608ULL) {
        zqMode = 2; full = false;
        offProbs = offHidx = offDmean = offEnt = offAlign = offTrans = OFF_DISABLED;
    } else if (out_n == 16777216ULL) {
        zqMode = 1; full = false;
        offProbs = offHidx = offDmean = offEnt = offAlign = offTrans = OFF_DISABLED;
    } else if (out_n == 75530243ULL) {
        zqMode = 2; full = true;
        offProbs = 8388608ULL;
        offHidx  = offProbs + 67108864ULL;
        offDmean = offHidx + 16384ULL;
        offEnt   = offDmean + 1ULL;
        offAlign = offEnt + 16384ULL;
        offTrans = offAlign + 1ULL;
    } else {
        zqMode = 0; full = true;
        offProbs = 16777216ULL;
        offHidx  = offProbs + 67108864ULL;
        offDmean = offHidx + 16384ULL;
        offEnt   = offDmean + 1ULL;
        offAlign = offEnt + 16384ULL;
        offTrans = offAlign + 1ULL;
    }

    void *ppB16 = nullptr, *pTtB = nullptr, *pMtB = nullptr,
         *pA3d = nullptr, *pB3d = nullptr, *pA3z = nullptr, *pB3z = nullptr;
    cudaGetSymbolAddress(&ppB16, g_pB16);
    cudaGetSymbolAddress(&pTtB, g_TtB16);
    cudaGetSymbolAddress(&pMtB, g_MtB16);
    cudaGetSymbolAddress(&pA3d, g_A3d);
    cudaGetSymbolAddress(&pB3d, g_B3d);
    cudaGetSymbolAddress(&pA3z, g_A3z);
    cudaGetSymbolAddress(&pB3z, g_B3z);

    const int SMEM = 3 * STAGE_BYTES;  // 147456
    cudaFuncSetAttribute(gemm_fused, cudaFuncAttributeMaxDynamicSharedMemorySize, SMEM);
    cudaFuncSetAttribute(gemm_meta,  cudaFuncAttributeMaxDynamicSharedMemorySize, SMEM);
    cudaFuncSetAttribute(gemm_zq,    cudaFuncAttributeMaxDynamicSharedMemorySize, SMEM);

    init_kernel<<<8, 256>>>();
    prep_kernel<<<M_ROWS, 256>>>(zr, zi);
    cb_rows_kernel<<<NS, 256>>>(cb);
    colsumF_kernel<<<dim3(4, 16), 256>>>();
    colsumC_kernel<<<dim3(4, 16), 256>>>(cb);
    c1_kernel<<<1, 1>>>();

    conv_p_kernel<<<65536, 256>>>(pprev);
    dim3 tb(32, 8);
    transpose_bf16<0><<<dim3(128, 128), tb>>>(T);
    if (full) transpose_bf16<1><<<dim3(128, 128), tb>>>(MT);
    transpose_cb_split<<<dim3(32, 128), tb>>>(cb);

    // fused: logits = c1*sig(p@T^T) + 2*flat@cb - rn - cn
    gemm_fused<<<dim3(16, 128), 256, SMEM>>>(
        (const __nv_bfloat16*)ppB16, (const __nv_bfloat16*)pTtB,
        (const __nv_bfloat16*)pA3d, (const __nv_bfloat16*)pB3d);
    // meta bias sum
    if (full)
        gemm_meta<<<dim3(16, 128), 256, SMEM>>>(
            (const __nv_bfloat16*)ppB16, (const __nv_bfloat16*)pMtB);
    // softmax + A3z build
    softmax_kernel<<<M_ROWS, 256>>>(pent, out, out_n, offProbs, offHidx, offEnt);
    // z_q
    gemm_zq<<<dim3(4, 128), 256, SMEM>>>(
        (const __nv_bfloat16*)pA3z, (const __nv_bfloat16*)pB3z, out, out_n, zqMode);

    if (full) {
        anchor_kernel<<<512, 256>>>(out + offProbs, EA, W, bv);
        final_kernel<<<1, 256>>>(out, out_n, offDmean, offAlign, offTrans);
    }
}